// round 5
// baseline (speedup 1.0000x reference)
#include <cuda_runtime.h>

#define NV   16000
#define PPV  32
#define CIN  10
#define NB   16000
#define BH   496
#define BW   432
#define OUTWH (BW*BH)          // 214272
#define OUTSZ (128*OUTWH)      // 27426816

// ---------------- static device scratch (no runtime allocation) ----------------
__device__ __align__(16) float g_voxelwise[NV * 64];   // [Nv][64]
__device__ __align__(16) float g_h2[NB * 512];         // [Nb][16][32]

extern __shared__ float sm_dyn[];

// mish(x) = x * tanh(softplus(x)) = x * t(t+2)/(t(t+2)+2), t = e^x
__device__ __forceinline__ float mishf(float x) {
    float t = __expf(fminf(x, 20.0f));
    float r = t * (t + 2.0f);
    return x * __fdividef(r, r + 2.0f);
}

// ============================================================================
// Kernel 0: zero the output map
// ============================================================================
__global__ void zero_kernel(float4* __restrict__ out, int n4) {
    int i = blockIdx.x * blockDim.x + threadIdx.x;
    if (i < n4) out[i] = make_float4(0.f, 0.f, 0.f, 0.f);
}

// ============================================================================
// Kernel 1: VFE. block=128 threads, thread=(pgrp:4 points, ogrp:4 outputs),
// VPB voxels per block (weights cached once in smem).
// ============================================================================
#define VPB 8
#define A_W1T 0        // [10][68]
#define A_W2T 680      // [64][68]
#define A_W3T 5032
#define A_W4T 9384
#define A_GB  13736    // 4 layers x (gamma64 | beta64)
#define A_XT  14248    // [64][36] transposed activations x[c][p]
#define A_MSK 16552    // [32]
#define A_SMEM_FLOATS 16584
#define A_SMEM_BYTES  (A_SMEM_FLOATS * 4)

template<int CINT>
__device__ __forceinline__ void fel_layer(
    const float* __restrict__ Wt, const float* __restrict__ gb,
    const float* __restrict__ xT, int p0, int o0, float (&y)[4][4])
{
    #pragma unroll
    for (int pi = 0; pi < 4; pi++)
        #pragma unroll
        for (int oi = 0; oi < 4; oi++) y[pi][oi] = 0.f;

    #pragma unroll 4
    for (int c = 0; c < CINT; c++) {
        float4 xv = *(const float4*)(xT + c*36 + p0);
        float4 wv = *(const float4*)(Wt + c*68 + o0);
        y[0][0] = fmaf(xv.x, wv.x, y[0][0]);
        y[0][1] = fmaf(xv.x, wv.y, y[0][1]);
        y[0][2] = fmaf(xv.x, wv.z, y[0][2]);
        y[0][3] = fmaf(xv.x, wv.w, y[0][3]);
        y[1][0] = fmaf(xv.y, wv.x, y[1][0]);
        y[1][1] = fmaf(xv.y, wv.y, y[1][1]);
        y[1][2] = fmaf(xv.y, wv.z, y[1][2]);
        y[1][3] = fmaf(xv.y, wv.w, y[1][3]);
        y[2][0] = fmaf(xv.z, wv.x, y[2][0]);
        y[2][1] = fmaf(xv.z, wv.y, y[2][1]);
        y[2][2] = fmaf(xv.z, wv.z, y[2][2]);
        y[2][3] = fmaf(xv.z, wv.w, y[2][3]);
        y[3][0] = fmaf(xv.w, wv.x, y[3][0]);
        y[3][1] = fmaf(xv.w, wv.y, y[3][1]);
        y[3][2] = fmaf(xv.w, wv.z, y[3][2]);
        y[3][3] = fmaf(xv.w, wv.w, y[3][3]);
    }
    // LayerNorm over 64 outputs per point (spread across 16 lanes x 4 regs)
    #pragma unroll
    for (int pi = 0; pi < 4; pi++) {
        float s  = y[pi][0] + y[pi][1] + y[pi][2] + y[pi][3];
        float ss = y[pi][0]*y[pi][0] + y[pi][1]*y[pi][1]
                 + y[pi][2]*y[pi][2] + y[pi][3]*y[pi][3];
        #pragma unroll
        for (int off = 8; off >= 1; off >>= 1) {
            s  += __shfl_xor_sync(0xffffffffu, s,  off);
            ss += __shfl_xor_sync(0xffffffffu, ss, off);
        }
        float m = s * (1.f/64.f);
        float r = rsqrtf(ss * (1.f/64.f) - m*m + 1e-5f);
        #pragma unroll
        for (int oi = 0; oi < 4; oi++) {
            float t = (y[pi][oi] - m) * r * gb[o0+oi] + gb[64+o0+oi];
            y[pi][oi] = mishf(t);
        }
    }
}

__global__ void __launch_bounds__(128, 3) vfe_kernel(
    const float* __restrict__ voxels, const float* __restrict__ voxelmask,
    const float* __restrict__ W1, const float* __restrict__ g1, const float* __restrict__ b1,
    const float* __restrict__ W2, const float* __restrict__ g2, const float* __restrict__ b2,
    const float* __restrict__ W3, const float* __restrict__ g3, const float* __restrict__ b3,
    const float* __restrict__ W4, const float* __restrict__ g4, const float* __restrict__ b4)
{
    float* sW1t = sm_dyn + A_W1T;
    float* sW2t = sm_dyn + A_W2T;
    float* sW3t = sm_dyn + A_W3T;
    float* sW4t = sm_dyn + A_W4T;
    float* sGB  = sm_dyn + A_GB;
    float* sXT  = sm_dyn + A_XT;
    float* sMsk = sm_dyn + A_MSK;

    const int tid = threadIdx.x;

    for (int i = tid; i < 64*CIN; i += 128) {
        int o = i / CIN, c = i - o*CIN;
        sW1t[c*68 + o] = W1[i];
    }
    for (int i = tid; i < 64*64; i += 128) {
        int o = i >> 6, c = i & 63;
        sW2t[c*68 + o] = W2[i];
        sW3t[c*68 + o] = W3[i];
        sW4t[c*68 + o] = W4[i];
    }
    if (tid < 64) {
        sGB[      tid] = g1[tid];  sGB[ 64 + tid] = b1[tid];
        sGB[128 + tid] = g2[tid];  sGB[192 + tid] = b2[tid];
        sGB[256 + tid] = g3[tid];  sGB[320 + tid] = b3[tid];
        sGB[384 + tid] = g4[tid];  sGB[448 + tid] = b4[tid];
    }

    const int pgrp = tid >> 4, ogrp = tid & 15;
    const int p0 = pgrp * 4,  o0 = ogrp * 4;

    for (int vb = 0; vb < VPB; vb++) {
        const int v = blockIdx.x * VPB + vb;
        __syncthreads();   // protect sXT reuse (also orders weight loads on vb==0)
        for (int i = tid; i < PPV*CIN; i += 128) {
            int p = i / CIN, c = i - p*CIN;
            sXT[c*36 + p] = voxels[v * (PPV*CIN) + i];
        }
        if (tid < PPV) sMsk[tid] = voxelmask[v*PPV + tid];
        __syncthreads();

        float msk[4];
        #pragma unroll
        for (int pi = 0; pi < 4; pi++) msk[pi] = sMsk[p0 + pi];

        float y[4][4], x2r[4][4];

        // ---- layer 1 (10 -> 64) ----
        fel_layer<CIN>(sW1t, sGB, sXT, p0, o0, y);
        __syncthreads();
        #pragma unroll
        for (int oi = 0; oi < 4; oi++)
            *(float4*)(sXT + (o0+oi)*36 + p0) =
                make_float4(y[0][oi], y[1][oi], y[2][oi], y[3][oi]);
        __syncthreads();

        // ---- layer 2 (* mask, keep residual) ----
        fel_layer<64>(sW2t, sGB + 128, sXT, p0, o0, y);
        #pragma unroll
        for (int pi = 0; pi < 4; pi++)
            #pragma unroll
            for (int oi = 0; oi < 4; oi++) {
                y[pi][oi] *= msk[pi];
                x2r[pi][oi] = y[pi][oi];
            }
        __syncthreads();
        #pragma unroll
        for (int oi = 0; oi < 4; oi++)
            *(float4*)(sXT + (o0+oi)*36 + p0) =
                make_float4(y[0][oi], y[1][oi], y[2][oi], y[3][oi]);
        __syncthreads();

        // ---- layer 3 ----
        fel_layer<64>(sW3t, sGB + 256, sXT, p0, o0, y);
        __syncthreads();
        #pragma unroll
        for (int oi = 0; oi < 4; oi++)
            *(float4*)(sXT + (o0+oi)*36 + p0) =
                make_float4(y[0][oi], y[1][oi], y[2][oi], y[3][oi]);
        __syncthreads();

        // ---- layer 4 (* mask + residual), then max over points ----
        fel_layer<64>(sW4t, sGB + 384, sXT, p0, o0, y);
        float mx[4];
        #pragma unroll
        for (int oi = 0; oi < 4; oi++) {
            #pragma unroll
            for (int pi = 0; pi < 4; pi++)
                y[pi][oi] = fmaf(y[pi][oi], msk[pi], x2r[pi][oi]);
            mx[oi] = fmaxf(fmaxf(y[0][oi], y[1][oi]), fmaxf(y[2][oi], y[3][oi]));
        }
        __syncthreads();
        #pragma unroll
        for (int oi = 0; oi < 4; oi++)
            sXT[(o0+oi)*36 + pgrp] = mx[oi];   // partial max scratch
        __syncthreads();
        if (tid < 64) {
            float m = sXT[tid*36];
            #pragma unroll
            for (int j = 1; j < 8; j++) m = fmaxf(m, sXT[tid*36 + j]);
            g_voxelwise[v*64 + tid] = m;
        }
    }
}

// ============================================================================
// Kernel 2: bfe1 + bevmask + bfe2a. grid=(125,16): blockIdx.y = branch g.
// block=128 threads = 32 cells x 4 p-slots. Thread-local LN (64 then 8).
// ============================================================================
#define B1_CELLS 32

__global__ void __launch_bounds__(128, 4) bev1_kernel(
    const int*   __restrict__ bevsidx, const float* __restrict__ bevmask,
    const float* __restrict__ W1,  const float* __restrict__ G1,  const float* __restrict__ Bb1,
    const float* __restrict__ W2a, const float* __restrict__ G2a, const float* __restrict__ B2a)
{
    __shared__ __align__(16) float sW1t[64*68];   // [v][o] transposed
    __shared__ __align__(16) float sW2a[512];     // [o8][c]
    __shared__ float sG1[64], sB1[64], sG2a[8], sB2a[8];
    __shared__ int   sidx[B1_CELLS*64];
    __shared__ float smask[B1_CELLS];

    const int tid = threadIdx.x;
    const int g = blockIdx.y;

    for (int i = tid; i < 4096; i += 128) {
        int o = i >> 6, v = i & 63;
        sW1t[v*68 + o] = W1[g*4096 + i];
    }
    for (int i = tid; i < 512; i += 128) sW2a[i] = W2a[g*512 + i];
    if (tid < 64) { sG1[tid] = G1[g*64 + tid]; sB1[tid] = Bb1[g*64 + tid]; }
    if (tid < 8)  { sG2a[tid] = G2a[g*8 + tid]; sB2a[tid] = B2a[g*8 + tid]; }

    const int cell = tid >> 2, p = tid & 3;
    const int c = g*4 + p;

    for (int n0 = blockIdx.x * B1_CELLS; n0 < NB; n0 += gridDim.x * B1_CELLS) {
        __syncthreads();
        for (int i = tid; i < B1_CELLS*64; i += 128)
            sidx[i] = bevsidx[n0*64 + i];
        if (tid < B1_CELLS) smask[tid] = bevmask[n0 + tid];
        __syncthreads();

        const int n = n0 + cell;
        const int* myidx = sidx + cell*64;

        float y[64];
        #pragma unroll
        for (int o = 0; o < 64; o++) y[o] = 0.f;

        // gather (2-deep prefetch) + rank-1 update into 64 accumulators
        float x0 = g_voxelwise[myidx[0]*64 + c];
        float x1 = g_voxelwise[myidx[1]*64 + c];
        for (int v = 0; v < 64; v++) {
            float xv = x0;
            x0 = x1;
            if (v + 2 < 64) x1 = g_voxelwise[myidx[v+2]*64 + c];
            const float* wr = sW1t + v*68;
            #pragma unroll
            for (int o = 0; o < 64; o += 4) {
                float4 w = *(const float4*)(wr + o);
                y[o+0] = fmaf(xv, w.x, y[o+0]);
                y[o+1] = fmaf(xv, w.y, y[o+1]);
                y[o+2] = fmaf(xv, w.z, y[o+2]);
                y[o+3] = fmaf(xv, w.w, y[o+3]);
            }
        }

        // LN(64) local + mish + bevmask
        float s = 0.f, ss = 0.f;
        #pragma unroll
        for (int o = 0; o < 64; o++) { s += y[o]; ss += y[o]*y[o]; }
        float m = s * (1.f/64.f);
        float r = rsqrtf(ss * (1.f/64.f) - m*m + 1e-5f);
        float mk = smask[cell];
        #pragma unroll
        for (int o = 0; o < 64; o++)
            y[o] = mishf((y[o] - m) * r * sG1[o] + sB1[o]) * mk;

        // bfe2a: 8 outputs over 64 channels, LN(8) local + mish
        float z[8];
        float s2 = 0.f, ss2 = 0.f;
        #pragma unroll
        for (int o8 = 0; o8 < 8; o8++) {
            float a = 0.f;
            const float* wr = sW2a + o8*64;
            #pragma unroll
            for (int cc = 0; cc < 64; cc += 4) {
                float4 w = *(const float4*)(wr + cc);
                a = fmaf(y[cc+0], w.x, a);
                a = fmaf(y[cc+1], w.y, a);
                a = fmaf(y[cc+2], w.z, a);
                a = fmaf(y[cc+3], w.w, a);
            }
            z[o8] = a; s2 += a; ss2 += a*a;
        }
        float m2 = s2 * 0.125f;
        float r2 = rsqrtf(ss2 * 0.125f - m2*m2 + 1e-5f);
        float* dst = g_h2 + n*512 + g*32 + p*8;
        #pragma unroll
        for (int o8 = 0; o8 < 8; o8++)
            dst[o8] = mishf((z[o8] - m2) * r2 * sG2a[o8] + sB2a[o8]);
    }
}

// ============================================================================
// Kernel 3: bfe2b + bfe3(x2) + residual + scatter. 2 cells/block, thread=channel.
// ============================================================================
#define B2_SMEM_FLOATS 23568
#define B2_SMEM_BYTES  (B2_SMEM_FLOATS * 4)

__device__ __forceinline__ void block_ln_stats(
    float zA, float zB, float* sred, int lane, int warp,
    float& mA, float& rA, float& mB, float& rB)
{
    float sA = zA, qA = zA*zA, sB = zB, qB = zB*zB;
    #pragma unroll
    for (int off = 16; off >= 1; off >>= 1) {
        sA += __shfl_xor_sync(0xffffffffu, sA, off);
        qA += __shfl_xor_sync(0xffffffffu, qA, off);
        sB += __shfl_xor_sync(0xffffffffu, sB, off);
        qB += __shfl_xor_sync(0xffffffffu, qB, off);
    }
    if (lane == 0) {
        sred[warp*4+0] = sA; sred[warp*4+1] = qA;
        sred[warp*4+2] = sB; sred[warp*4+3] = qB;
    }
    __syncthreads();
    sA = sred[0] + sred[4] + sred[8]  + sred[12];
    qA = sred[1] + sred[5] + sred[9]  + sred[13];
    sB = sred[2] + sred[6] + sred[10] + sred[14];
    qB = sred[3] + sred[7] + sred[11] + sred[15];
    __syncthreads();   // sred reusable
    mA = sA * (1.f/128.f);  mB = sB * (1.f/128.f);
    rA = rsqrtf(qA * (1.f/128.f) - mA*mA + 1e-5f);
    rB = rsqrtf(qB * (1.f/128.f) - mB*mB + 1e-5f);
}

__global__ void __launch_bounds__(128) bev2_kernel(
    const float* __restrict__ W2b, const float* __restrict__ G2b, const float* __restrict__ B2b,
    const float* __restrict__ W3,  const float* __restrict__ G3,  const float* __restrict__ B3,
    const int*   __restrict__ bevcoors,
    float* __restrict__ out)
{
    float* sW2b = sm_dyn;             // 128 x 36 (padded)
    float* sW3  = sm_dyn + 4608;      // 128 x 132 (padded)
    float* sG2b = sm_dyn + 21504;
    float* sB2b = sm_dyn + 21632;
    float* sG3  = sm_dyn + 21760;
    float* sB3  = sm_dyn + 21888;
    float* sH   = sm_dyn + 22016;     // 2 x 512
    float* s17  = sm_dyn + 23040;     // 2 x 128
    float* s18  = sm_dyn + 23296;     // 2 x 128
    float* sred = sm_dyn + 23552;     // 16

    const int t = threadIdx.x;
    const int lane = t & 31, warp = t >> 5;
    const int g = t >> 3;

    for (int i = t; i < 128*32; i += 128) {
        int o = i >> 5, c = i & 31;
        sW2b[o*36 + c] = W2b[i];
    }
    for (int i = t; i < 128*128; i += 128) {
        int o = i >> 7, c = i & 127;
        sW3[o*132 + c] = W3[i];
    }
    sG2b[t] = G2b[t]; sB2b[t] = B2b[t];
    sG3[t]  = G3[t];  sB3[t]  = B3[t];

    for (int pair = blockIdx.x; pair < NB/2; pair += gridDim.x) {
        const int nA = pair*2, nB = pair*2 + 1;
        __syncthreads();   // protect sH/s17/s18 reuse
        for (int i = t; i < 1024; i += 128)
            sH[i] = g_h2[nA*512 + i];
        __syncthreads();

        // ---- bfe2b: thread (g=t/8, o8=t%8) ----
        float aA = 0.f, aB = 0.f;
        {
            const float* wr = sW2b + t*36;
            const float* ha = sH + g*32;
            const float* hb = ha + 512;
            #pragma unroll
            for (int c = 0; c < 32; c += 4) {
                float4 w  = *(const float4*)(wr + c);
                float4 xa = *(const float4*)(ha + c);
                float4 xb = *(const float4*)(hb + c);
                aA = fmaf(xa.x, w.x, aA); aA = fmaf(xa.y, w.y, aA);
                aA = fmaf(xa.z, w.z, aA); aA = fmaf(xa.w, w.w, aA);
                aB = fmaf(xb.x, w.x, aB); aB = fmaf(xb.y, w.y, aB);
                aB = fmaf(xb.z, w.z, aB); aB = fmaf(xb.w, w.w, aB);
            }
        }
        // LN over 8 (lane groups of 8)
        float sA = aA, qA = aA*aA, sB = aB, qB = aB*aB;
        #pragma unroll
        for (int off = 4; off >= 1; off >>= 1) {
            sA += __shfl_xor_sync(0xffffffffu, sA, off);
            qA += __shfl_xor_sync(0xffffffffu, qA, off);
            sB += __shfl_xor_sync(0xffffffffu, sB, off);
            qB += __shfl_xor_sync(0xffffffffu, qB, off);
        }
        float mA = sA * 0.125f, mB = sB * 0.125f;
        float rA = rsqrtf(qA * 0.125f - mA*mA + 1e-5f);
        float rB = rsqrtf(qB * 0.125f - mB*mB + 1e-5f);
        float x17A = mishf((aA - mA) * rA * sG2b[t] + sB2b[t]);
        float x17B = mishf((aB - mB) * rB * sG2b[t] + sB2b[t]);
        s17[t] = x17A; s17[128 + t] = x17B;
        __syncthreads();

        const float* wr3 = sW3 + t*132;

        // ---- bfe3 layer 1 ----
        float zA = 0.f, zB = 0.f;
        #pragma unroll 8
        for (int c = 0; c < 128; c += 4) {
            float4 w  = *(const float4*)(wr3 + c);
            float4 xa = *(const float4*)(s17 + c);
            float4 xb = *(const float4*)(s17 + 128 + c);
            zA = fmaf(xa.x, w.x, zA); zA = fmaf(xa.y, w.y, zA);
            zA = fmaf(xa.z, w.z, zA); zA = fmaf(xa.w, w.w, zA);
            zB = fmaf(xb.x, w.x, zB); zB = fmaf(xb.y, w.y, zB);
            zB = fmaf(xb.z, w.z, zB); zB = fmaf(xb.w, w.w, zB);
        }
        block_ln_stats(zA, zB, sred, lane, warp, mA, rA, mB, rB);
        float x18A = mishf((zA - mA) * rA * sG3[t] + sB3[t]);
        float x18B = mishf((zB - mB) * rB * sG3[t] + sB3[t]);
        s18[t] = x18A; s18[128 + t] = x18B;
        __syncthreads();

        // ---- bfe3 layer 2 + residual ----
        zA = 0.f; zB = 0.f;
        #pragma unroll 8
        for (int c = 0; c < 128; c += 4) {
            float4 w  = *(const float4*)(wr3 + c);
            float4 xa = *(const float4*)(s18 + c);
            float4 xb = *(const float4*)(s18 + 128 + c);
            zA = fmaf(xa.x, w.x, zA); zA = fmaf(xa.y, w.y, zA);
            zA = fmaf(xa.z, w.z, zA); zA = fmaf(xa.w, w.w, zA);
            zB = fmaf(xb.x, w.x, zB); zB = fmaf(xb.y, w.y, zB);
            zB = fmaf(xb.z, w.z, zB); zB = fmaf(xb.w, w.w, zB);
        }
        block_ln_stats(zA, zB, sred, lane, warp, mA, rA, mB, rB);
        float x19A = mishf((zA - mA) * rA * sG3[t] + sB3[t]) + x17A;
        float x19B = mishf((zB - mB) * rB * sG3[t] + sB3[t]) + x17B;

        // ---- scatter: out[ch][w][h] ----
        int2 ca = ((const int2*)bevcoors)[nA];
        int2 cb = ((const int2*)bevcoors)[nB];
        out[t*OUTWH + ca.y*BH + ca.x] = x19A;
        out[t*OUTWH + cb.y*BH + cb.x] = x19B;
    }
}

// ============================================================================
// launch
// ============================================================================
extern "C" void kernel_launch(void* const* d_in, const int* in_sizes, int n_in,
                              void* d_out, int out_size)
{
    (void)in_sizes; (void)n_in; (void)out_size;

    const float* voxels    = (const float*)d_in[0];
    const float* voxelmask = (const float*)d_in[1];
    const int*   bevsidx   = (const int*)d_in[2];
    const int*   bevcoors  = (const int*)d_in[3];
    const float* bevmask   = (const float*)d_in[4];
    float* out = (float*)d_out;

    cudaFuncSetAttribute(vfe_kernel,  cudaFuncAttributeMaxDynamicSharedMemorySize, A_SMEM_BYTES);
    cudaFuncSetAttribute(bev2_kernel, cudaFuncAttributeMaxDynamicSharedMemorySize, B2_SMEM_BYTES);

    zero_kernel<<<(OUTSZ/4 + 255)/256, 256>>>((float4*)out, OUTSZ/4);

    vfe_kernel<<<NV/VPB, 128, A_SMEM_BYTES>>>(
        voxels, voxelmask,
        (const float*)d_in[5],  (const float*)d_in[6],  (const float*)d_in[7],
        (const float*)d_in[8],  (const float*)d_in[9],  (const float*)d_in[10],
        (const float*)d_in[11], (const float*)d_in[12], (const float*)d_in[13],
        (const float*)d_in[14], (const float*)d_in[15], (const float*)d_in[16]);

    bev1_kernel<<<dim3(125, 16), 128>>>(
        bevsidx, bevmask,
        (const float*)d_in[17], (const float*)d_in[18], (const float*)d_in[19],
        (const float*)d_in[20], (const float*)d_in[21], (const float*)d_in[22]);

    bev2_kernel<<<1000, 128, B2_SMEM_BYTES>>>(
        (const float*)d_in[23], (const float*)d_in[24], (const float*)d_in[25],
        (const float*)d_in[26], (const float*)d_in[27], (const float*)d_in[28],
        bevcoors, out);
}

// round 6
// speedup vs baseline: 1.0501x; 1.0501x over previous
#include <cuda_runtime.h>

#define NV   16000
#define PPV  32
#define CIN  10
#define NB   16000
#define BH   496
#define BW   432
#define OUTWH (BW*BH)          // 214272
#define OUTSZ (128*OUTWH)      // 27426816

// ---------------- static device scratch (no runtime allocation) ----------------
__device__ __align__(16) float g_voxelwise[NV * 64];   // [Nv][64]
__device__ __align__(16) float g_h2[NB * 512];         // [Nb][16][32]

extern __shared__ float sm_dyn[];

// mish(x) = x * tanh(softplus(x)) = x * t(t+2)/(t(t+2)+2), t = e^x
__device__ __forceinline__ float mishf(float x) {
    float t = __expf(fminf(x, 20.0f));
    float r = t * (t + 2.0f);
    return x * __fdividef(r, r + 2.0f);
}

// packed f32x2 FMA: d = a*b + d (elementwise, rn) — sm_100+ FFMA2
__device__ __forceinline__ void fma2(float2& d, const float2 a, const float2 b) {
    asm("fma.rn.f32x2 %0, %1, %2, %0;"
        : "+l"(reinterpret_cast<unsigned long long&>(d))
        : "l"(reinterpret_cast<const unsigned long long&>(a)),
          "l"(reinterpret_cast<const unsigned long long&>(b)));
}

// ============================================================================
// Kernel 0: zero the output map
// ============================================================================
__global__ void zero_kernel(float4* __restrict__ out, int n4) {
    int i = blockIdx.x * blockDim.x + threadIdx.x;
    if (i < n4) out[i] = make_float4(0.f, 0.f, 0.f, 0.f);
}

// ============================================================================
// Kernel 1: VFE. block=128 threads, thread=(pgrp:4 points, ogrp:4 outputs),
// VPB voxels per block (weights cached once in smem). Inner GEMM uses FFMA2
// packed along point pairs.
// ============================================================================
#define VPB 8
#define A_W1T 0        // [10][68]
#define A_W2T 680      // [64][68]
#define A_W3T 5032
#define A_W4T 9384
#define A_GB  13736    // 4 layers x (gamma64 | beta64)
#define A_XT  14248    // [64][36] transposed activations x[c][p]
#define A_MSK 16552    // [32]
#define A_SMEM_FLOATS 16584
#define A_SMEM_BYTES  (A_SMEM_FLOATS * 4)

template<int CINT>
__device__ __forceinline__ void fel_layer(
    const float* __restrict__ Wt, const float* __restrict__ gb,
    const float* __restrict__ xT, int p0, int o0, float (&y)[4][4])
{
    float2 acc[2][4];
    #pragma unroll
    for (int pj = 0; pj < 2; pj++)
        #pragma unroll
        for (int oi = 0; oi < 4; oi++) acc[pj][oi] = make_float2(0.f, 0.f);

    #pragma unroll 4
    for (int c = 0; c < CINT; c++) {
        float4 xv = *(const float4*)(xT + c*36 + p0);
        float4 wv = *(const float4*)(Wt + c*68 + o0);
        float2 x01 = make_float2(xv.x, xv.y);
        float2 x23 = make_float2(xv.z, xv.w);
        float2 w0 = make_float2(wv.x, wv.x);
        float2 w1 = make_float2(wv.y, wv.y);
        float2 w2 = make_float2(wv.z, wv.z);
        float2 w3 = make_float2(wv.w, wv.w);
        fma2(acc[0][0], x01, w0);
        fma2(acc[0][1], x01, w1);
        fma2(acc[0][2], x01, w2);
        fma2(acc[0][3], x01, w3);
        fma2(acc[1][0], x23, w0);
        fma2(acc[1][1], x23, w1);
        fma2(acc[1][2], x23, w2);
        fma2(acc[1][3], x23, w3);
    }
    #pragma unroll
    for (int oi = 0; oi < 4; oi++) {
        y[0][oi] = acc[0][oi].x;
        y[1][oi] = acc[0][oi].y;
        y[2][oi] = acc[1][oi].x;
        y[3][oi] = acc[1][oi].y;
    }
    // LayerNorm over 64 outputs per point (spread across 16 lanes x 4 regs)
    #pragma unroll
    for (int pi = 0; pi < 4; pi++) {
        float s  = y[pi][0] + y[pi][1] + y[pi][2] + y[pi][3];
        float ss = y[pi][0]*y[pi][0] + y[pi][1]*y[pi][1]
                 + y[pi][2]*y[pi][2] + y[pi][3]*y[pi][3];
        #pragma unroll
        for (int off = 8; off >= 1; off >>= 1) {
            s  += __shfl_xor_sync(0xffffffffu, s,  off);
            ss += __shfl_xor_sync(0xffffffffu, ss, off);
        }
        float m = s * (1.f/64.f);
        float r = rsqrtf(ss * (1.f/64.f) - m*m + 1e-5f);
        #pragma unroll
        for (int oi = 0; oi < 4; oi++) {
            float t = (y[pi][oi] - m) * r * gb[o0+oi] + gb[64+o0+oi];
            y[pi][oi] = mishf(t);
        }
    }
}

__global__ void __launch_bounds__(128, 3) vfe_kernel(
    const float* __restrict__ voxels, const float* __restrict__ voxelmask,
    const float* __restrict__ W1, const float* __restrict__ g1, const float* __restrict__ b1,
    const float* __restrict__ W2, const float* __restrict__ g2, const float* __restrict__ b2,
    const float* __restrict__ W3, const float* __restrict__ g3, const float* __restrict__ b3,
    const float* __restrict__ W4, const float* __restrict__ g4, const float* __restrict__ b4)
{
    float* sW1t = sm_dyn + A_W1T;
    float* sW2t = sm_dyn + A_W2T;
    float* sW3t = sm_dyn + A_W3T;
    float* sW4t = sm_dyn + A_W4T;
    float* sGB  = sm_dyn + A_GB;
    float* sXT  = sm_dyn + A_XT;
    float* sMsk = sm_dyn + A_MSK;

    const int tid = threadIdx.x;

    for (int i = tid; i < 64*CIN; i += 128) {
        int o = i / CIN, c = i - o*CIN;
        sW1t[c*68 + o] = W1[i];
    }
    for (int i = tid; i < 64*64; i += 128) {
        int o = i >> 6, c = i & 63;
        sW2t[c*68 + o] = W2[i];
        sW3t[c*68 + o] = W3[i];
        sW4t[c*68 + o] = W4[i];
    }
    if (tid < 64) {
        sGB[      tid] = g1[tid];  sGB[ 64 + tid] = b1[tid];
        sGB[128 + tid] = g2[tid];  sGB[192 + tid] = b2[tid];
        sGB[256 + tid] = g3[tid];  sGB[320 + tid] = b3[tid];
        sGB[384 + tid] = g4[tid];  sGB[448 + tid] = b4[tid];
    }

    const int pgrp = tid >> 4, ogrp = tid & 15;
    const int p0 = pgrp * 4,  o0 = ogrp * 4;

    for (int vb = 0; vb < VPB; vb++) {
        const int v = blockIdx.x * VPB + vb;
        __syncthreads();   // protect sXT reuse (also orders weight loads on vb==0)
        for (int i = tid; i < PPV*CIN; i += 128) {
            int p = i / CIN, c = i - p*CIN;
            sXT[c*36 + p] = voxels[v * (PPV*CIN) + i];
        }
        if (tid < PPV) sMsk[tid] = voxelmask[v*PPV + tid];
        __syncthreads();

        float msk[4];
        #pragma unroll
        for (int pi = 0; pi < 4; pi++) msk[pi] = sMsk[p0 + pi];

        float y[4][4], x2r[4][4];

        // ---- layer 1 (10 -> 64) ----
        fel_layer<CIN>(sW1t, sGB, sXT, p0, o0, y);
        __syncthreads();
        #pragma unroll
        for (int oi = 0; oi < 4; oi++)
            *(float4*)(sXT + (o0+oi)*36 + p0) =
                make_float4(y[0][oi], y[1][oi], y[2][oi], y[3][oi]);
        __syncthreads();

        // ---- layer 2 (* mask, keep residual) ----
        fel_layer<64>(sW2t, sGB + 128, sXT, p0, o0, y);
        #pragma unroll
        for (int pi = 0; pi < 4; pi++)
            #pragma unroll
            for (int oi = 0; oi < 4; oi++) {
                y[pi][oi] *= msk[pi];
                x2r[pi][oi] = y[pi][oi];
            }
        __syncthreads();
        #pragma unroll
        for (int oi = 0; oi < 4; oi++)
            *(float4*)(sXT + (o0+oi)*36 + p0) =
                make_float4(y[0][oi], y[1][oi], y[2][oi], y[3][oi]);
        __syncthreads();

        // ---- layer 3 ----
        fel_layer<64>(sW3t, sGB + 256, sXT, p0, o0, y);
        __syncthreads();
        #pragma unroll
        for (int oi = 0; oi < 4; oi++)
            *(float4*)(sXT + (o0+oi)*36 + p0) =
                make_float4(y[0][oi], y[1][oi], y[2][oi], y[3][oi]);
        __syncthreads();

        // ---- layer 4 (* mask + residual), then max over points ----
        fel_layer<64>(sW4t, sGB + 384, sXT, p0, o0, y);
        float mx[4];
        #pragma unroll
        for (int oi = 0; oi < 4; oi++) {
            #pragma unroll
            for (int pi = 0; pi < 4; pi++)
                y[pi][oi] = fmaf(y[pi][oi], msk[pi], x2r[pi][oi]);
            mx[oi] = fmaxf(fmaxf(y[0][oi], y[1][oi]), fmaxf(y[2][oi], y[3][oi]));
        }
        __syncthreads();
        #pragma unroll
        for (int oi = 0; oi < 4; oi++)
            sXT[(o0+oi)*36 + pgrp] = mx[oi];   // partial max scratch
        __syncthreads();
        if (tid < 64) {
            float m = sXT[tid*36];
            #pragma unroll
            for (int j = 1; j < 8; j++) m = fmaxf(m, sXT[tid*36 + j]);
            g_voxelwise[v*64 + tid] = m;
        }
    }
}

// ============================================================================
// Kernel 2: bfe1 + bevmask + bfe2a. grid=(125,16): blockIdx.y = branch g.
// block=128 threads = 32 cells x 4 p-slots. Thread-local LN (64 then 8).
// Inner GEMMs use FFMA2 packed along outputs / channels.
// ============================================================================
#define B1_CELLS 32

__global__ void __launch_bounds__(128, 4) bev1_kernel(
    const int*   __restrict__ bevsidx, const float* __restrict__ bevmask,
    const float* __restrict__ W1,  const float* __restrict__ G1,  const float* __restrict__ Bb1,
    const float* __restrict__ W2a, const float* __restrict__ G2a, const float* __restrict__ B2a)
{
    __shared__ __align__(16) float sW1t[64*68];   // [v][o] transposed
    __shared__ __align__(16) float sW2a[512];     // [o8][c]
    __shared__ float sG1[64], sB1[64], sG2a[8], sB2a[8];
    __shared__ int   sidx[B1_CELLS*64];
    __shared__ float smask[B1_CELLS];

    const int tid = threadIdx.x;
    const int g = blockIdx.y;

    for (int i = tid; i < 4096; i += 128) {
        int o = i >> 6, v = i & 63;
        sW1t[v*68 + o] = W1[g*4096 + i];
    }
    for (int i = tid; i < 512; i += 128) sW2a[i] = W2a[g*512 + i];
    if (tid < 64) { sG1[tid] = G1[g*64 + tid]; sB1[tid] = Bb1[g*64 + tid]; }
    if (tid < 8)  { sG2a[tid] = G2a[g*8 + tid]; sB2a[tid] = B2a[g*8 + tid]; }

    const int cell = tid >> 2, p = tid & 3;
    const int c = g*4 + p;

    for (int n0 = blockIdx.x * B1_CELLS; n0 < NB; n0 += gridDim.x * B1_CELLS) {
        __syncthreads();
        for (int i = tid; i < B1_CELLS*64; i += 128)
            sidx[i] = bevsidx[n0*64 + i];
        if (tid < B1_CELLS) smask[tid] = bevmask[n0 + tid];
        __syncthreads();

        const int n = n0 + cell;
        const int* myidx = sidx + cell*64;

        float2 y2[32];   // packed output pairs (o, o+1)
        #pragma unroll
        for (int i = 0; i < 32; i++) y2[i] = make_float2(0.f, 0.f);

        // gather (2-deep prefetch) + rank-1 update into 32 packed accumulators
        float x0 = g_voxelwise[myidx[0]*64 + c];
        float x1 = g_voxelwise[myidx[1]*64 + c];
        #pragma unroll 2
        for (int v = 0; v < 64; v++) {
            float xv = x0;
            x0 = x1;
            if (v + 2 < 64) x1 = g_voxelwise[myidx[v+2]*64 + c];
            float2 xb = make_float2(xv, xv);
            const float* wr = sW1t + v*68;
            #pragma unroll
            for (int o = 0; o < 64; o += 4) {
                float4 w = *(const float4*)(wr + o);
                fma2(y2[(o>>1)  ], xb, make_float2(w.x, w.y));
                fma2(y2[(o>>1)+1], xb, make_float2(w.z, w.w));
            }
        }

        // LN(64) local + mish + bevmask
        float s = 0.f, ss = 0.f;
        #pragma unroll
        for (int i = 0; i < 32; i++) {
            s  += y2[i].x + y2[i].y;
            ss += y2[i].x*y2[i].x + y2[i].y*y2[i].y;
        }
        float m = s * (1.f/64.f);
        float r = rsqrtf(ss * (1.f/64.f) - m*m + 1e-5f);
        float mk = smask[cell];
        #pragma unroll
        for (int i = 0; i < 32; i++) {
            y2[i].x = mishf((y2[i].x - m) * r * sG1[2*i  ] + sB1[2*i  ]) * mk;
            y2[i].y = mishf((y2[i].y - m) * r * sG1[2*i+1] + sB1[2*i+1]) * mk;
        }

        // bfe2a: 8 outputs over 64 channels (packed along c), LN(8) local + mish
        float z[8];
        float s2 = 0.f, ss2 = 0.f;
        #pragma unroll
        for (int o8 = 0; o8 < 8; o8++) {
            float2 acc = make_float2(0.f, 0.f);
            const float* wr = sW2a + o8*64;
            #pragma unroll
            for (int cc = 0; cc < 64; cc += 4) {
                float4 w = *(const float4*)(wr + cc);
                fma2(acc, y2[(cc>>1)  ], make_float2(w.x, w.y));
                fma2(acc, y2[(cc>>1)+1], make_float2(w.z, w.w));
            }
            float a = acc.x + acc.y;
            z[o8] = a; s2 += a; ss2 += a*a;
        }
        float m2 = s2 * 0.125f;
        float r2 = rsqrtf(ss2 * 0.125f - m2*m2 + 1e-5f);
        float* dst = g_h2 + n*512 + g*32 + p*8;
        #pragma unroll
        for (int o8 = 0; o8 < 8; o8++)
            dst[o8] = mishf((z[o8] - m2) * r2 * sG2a[o8] + sB2a[o8]);
    }
}

// ============================================================================
// Kernel 3: bfe2b + bfe3(x2) + residual + scatter. 4 cells/iteration,
// thread=channel, GEMMs packed along c with FFMA2.
// ============================================================================
#define B2_SMEM_FLOATS 25120
#define B2_SMEM_BYTES  (B2_SMEM_FLOATS * 4)

__device__ __forceinline__ void block_ln4(
    const float z[4], float* sred, int lane, int warp,
    float m[4], float r[4])
{
    float s[4], q[4];
    #pragma unroll
    for (int k = 0; k < 4; k++) { s[k] = z[k]; q[k] = z[k]*z[k]; }
    #pragma unroll
    for (int off = 16; off >= 1; off >>= 1) {
        #pragma unroll
        for (int k = 0; k < 4; k++) {
            s[k] += __shfl_xor_sync(0xffffffffu, s[k], off);
            q[k] += __shfl_xor_sync(0xffffffffu, q[k], off);
        }
    }
    if (lane == 0) {
        #pragma unroll
        for (int k = 0; k < 4; k++) {
            sred[warp*8 + k]     = s[k];
            sred[warp*8 + 4 + k] = q[k];
        }
    }
    __syncthreads();
    #pragma unroll
    for (int k = 0; k < 4; k++) {
        s[k] = sred[k] + sred[8+k] + sred[16+k] + sred[24+k];
        q[k] = sred[4+k] + sred[12+k] + sred[20+k] + sred[28+k];
    }
    __syncthreads();   // sred reusable
    #pragma unroll
    for (int k = 0; k < 4; k++) {
        m[k] = s[k] * (1.f/128.f);
        r[k] = rsqrtf(q[k] * (1.f/128.f) - m[k]*m[k] + 1e-5f);
    }
}

__global__ void __launch_bounds__(128) bev2_kernel(
    const float* __restrict__ W2b, const float* __restrict__ G2b, const float* __restrict__ B2b,
    const float* __restrict__ W3,  const float* __restrict__ G3,  const float* __restrict__ B3,
    const int*   __restrict__ bevcoors,
    float* __restrict__ out)
{
    float* sW2b = sm_dyn;             // 128 x 36 (padded)
    float* sW3  = sm_dyn + 4608;      // 128 x 132 (padded)
    float* sG2b = sm_dyn + 21504;
    float* sB2b = sm_dyn + 21632;
    float* sG3  = sm_dyn + 21760;
    float* sB3  = sm_dyn + 21888;
    float* sH   = sm_dyn + 22016;     // 4 x 512
    float* s17  = sm_dyn + 24064;     // 4 x 128
    float* s18  = sm_dyn + 24576;     // 4 x 128
    float* sred = sm_dyn + 25088;     // 32

    const int t = threadIdx.x;
    const int lane = t & 31, warp = t >> 5;
    const int g = t >> 3;

    for (int i = t; i < 128*32; i += 128) {
        int o = i >> 5, c = i & 31;
        sW2b[o*36 + c] = W2b[i];
    }
    for (int i = t; i < 128*128; i += 128) {
        int o = i >> 7, c = i & 127;
        sW3[o*132 + c] = W3[i];
    }
    sG2b[t] = G2b[t]; sB2b[t] = B2b[t];
    sG3[t]  = G3[t];  sB3[t]  = B3[t];

    for (int quad = blockIdx.x; quad < NB/4; quad += gridDim.x) {
        const int n0 = quad * 4;
        __syncthreads();   // protect sH/s17/s18 reuse
        for (int i = t; i < 2048; i += 128)
            sH[i] = g_h2[n0*512 + i];
        __syncthreads();

        // ---- bfe2b: thread (g=t/8, o8=t%8), 4 cells, packed along c ----
        float2 a0 = {0.f,0.f}, a1 = {0.f,0.f}, a2 = {0.f,0.f}, a3 = {0.f,0.f};
        {
            const float* wr = sW2b + t*36;
            const float* h0 = sH + g*32;
            #pragma unroll
            for (int c = 0; c < 32; c += 4) {
                float4 w  = *(const float4*)(wr + c);
                float2 wlo = make_float2(w.x, w.y), whi = make_float2(w.z, w.w);
                float4 xa = *(const float4*)(h0 + c);
                float4 xb = *(const float4*)(h0 + 512 + c);
                float4 xc = *(const float4*)(h0 + 1024 + c);
                float4 xd = *(const float4*)(h0 + 1536 + c);
                fma2(a0, make_float2(xa.x, xa.y), wlo);
                fma2(a0, make_float2(xa.z, xa.w), whi);
                fma2(a1, make_float2(xb.x, xb.y), wlo);
                fma2(a1, make_float2(xb.z, xb.w), whi);
                fma2(a2, make_float2(xc.x, xc.y), wlo);
                fma2(a2, make_float2(xc.z, xc.w), whi);
                fma2(a3, make_float2(xd.x, xd.y), wlo);
                fma2(a3, make_float2(xd.z, xd.w), whi);
            }
        }
        float zz[4] = { a0.x + a0.y, a1.x + a1.y, a2.x + a2.y, a3.x + a3.y };

        // LN over 8 (lane groups of 8) per cell
        float x17[4];
        {
            float s[4], q[4];
            #pragma unroll
            for (int k = 0; k < 4; k++) { s[k] = zz[k]; q[k] = zz[k]*zz[k]; }
            #pragma unroll
            for (int off = 4; off >= 1; off >>= 1) {
                #pragma unroll
                for (int k = 0; k < 4; k++) {
                    s[k] += __shfl_xor_sync(0xffffffffu, s[k], off);
                    q[k] += __shfl_xor_sync(0xffffffffu, q[k], off);
                }
            }
            #pragma unroll
            for (int k = 0; k < 4; k++) {
                float mm = s[k] * 0.125f;
                float rr = rsqrtf(q[k] * 0.125f - mm*mm + 1e-5f);
                x17[k] = mishf((zz[k] - mm) * rr * sG2b[t] + sB2b[t]);
                s17[k*128 + t] = x17[k];
            }
        }
        __syncthreads();

        const float* wr3 = sW3 + t*132;

        // ---- bfe3 layer 1 (packed along c) ----
        a0 = make_float2(0.f,0.f); a1 = make_float2(0.f,0.f);
        a2 = make_float2(0.f,0.f); a3 = make_float2(0.f,0.f);
        #pragma unroll 8
        for (int c = 0; c < 128; c += 4) {
            float4 w  = *(const float4*)(wr3 + c);
            float2 wlo = make_float2(w.x, w.y), whi = make_float2(w.z, w.w);
            float4 xa = *(const float4*)(s17 + c);
            float4 xb = *(const float4*)(s17 + 128 + c);
            float4 xc = *(const float4*)(s17 + 256 + c);
            float4 xd = *(const float4*)(s17 + 384 + c);
            fma2(a0, make_float2(xa.x, xa.y), wlo);
            fma2(a0, make_float2(xa.z, xa.w), whi);
            fma2(a1, make_float2(xb.x, xb.y), wlo);
            fma2(a1, make_float2(xb.z, xb.w), whi);
            fma2(a2, make_float2(xc.x, xc.y), wlo);
            fma2(a2, make_float2(xc.z, xc.w), whi);
            fma2(a3, make_float2(xd.x, xd.y), wlo);
            fma2(a3, make_float2(xd.z, xd.w), whi);
        }
        zz[0] = a0.x + a0.y; zz[1] = a1.x + a1.y;
        zz[2] = a2.x + a2.y; zz[3] = a3.x + a3.y;
        {
            float m[4], r[4];
            block_ln4(zz, sred, lane, warp, m, r);
            #pragma unroll
            for (int k = 0; k < 4; k++)
                s18[k*128 + t] = mishf((zz[k] - m[k]) * r[k] * sG3[t] + sB3[t]);
        }
        __syncthreads();

        // ---- bfe3 layer 2 + residual ----
        a0 = make_float2(0.f,0.f); a1 = make_float2(0.f,0.f);
        a2 = make_float2(0.f,0.f); a3 = make_float2(0.f,0.f);
        #pragma unroll 8
        for (int c = 0; c < 128; c += 4) {
            float4 w  = *(const float4*)(wr3 + c);
            float2 wlo = make_float2(w.x, w.y), whi = make_float2(w.z, w.w);
            float4 xa = *(const float4*)(s18 + c);
            float4 xb = *(const float4*)(s18 + 128 + c);
            float4 xc = *(const float4*)(s18 + 256 + c);
            float4 xd = *(const float4*)(s18 + 384 + c);
            fma2(a0, make_float2(xa.x, xa.y), wlo);
            fma2(a0, make_float2(xa.z, xa.w), whi);
            fma2(a1, make_float2(xb.x, xb.y), wlo);
            fma2(a1, make_float2(xb.z, xb.w), whi);
            fma2(a2, make_float2(xc.x, xc.y), wlo);
            fma2(a2, make_float2(xc.z, xc.w), whi);
            fma2(a3, make_float2(xd.x, xd.y), wlo);
            fma2(a3, make_float2(xd.z, xd.w), whi);
        }
        zz[0] = a0.x + a0.y; zz[1] = a1.x + a1.y;
        zz[2] = a2.x + a2.y; zz[3] = a3.x + a3.y;
        {
            float m[4], r[4];
            block_ln4(zz, sred, lane, warp, m, r);
            #pragma unroll
            for (int k = 0; k < 4; k++) {
                float x19 = mishf((zz[k] - m[k]) * r[k] * sG3[t] + sB3[t]) + x17[k];
                int2 cc = ((const int2*)bevcoors)[n0 + k];
                out[t*OUTWH + cc.y*BH + cc.x] = x19;
            }
        }
    }
}

// ============================================================================
// launch
// ============================================================================
extern "C" void kernel_launch(void* const* d_in, const int* in_sizes, int n_in,
                              void* d_out, int out_size)
{
    (void)in_sizes; (void)n_in; (void)out_size;

    const float* voxels    = (const float*)d_in[0];
    const float* voxelmask = (const float*)d_in[1];
    const int*   bevsidx   = (const int*)d_in[2];
    const int*   bevcoors  = (const int*)d_in[3];
    const float* bevmask   = (const float*)d_in[4];
    float* out = (float*)d_out;

    cudaFuncSetAttribute(vfe_kernel,  cudaFuncAttributeMaxDynamicSharedMemorySize, A_SMEM_BYTES);
    cudaFuncSetAttribute(bev2_kernel, cudaFuncAttributeMaxDynamicSharedMemorySize, B2_SMEM_BYTES);

    zero_kernel<<<(OUTSZ/4 + 255)/256, 256>>>((float4*)out, OUTSZ/4);

    vfe_kernel<<<NV/VPB, 128, A_SMEM_BYTES>>>(
        voxels, voxelmask,
        (const float*)d_in[5],  (const float*)d_in[6],  (const float*)d_in[7],
        (const float*)d_in[8],  (const float*)d_in[9],  (const float*)d_in[10],
        (const float*)d_in[11], (const float*)d_in[12], (const float*)d_in[13],
        (const float*)d_in[14], (const float*)d_in[15], (const float*)d_in[16]);

    bev1_kernel<<<dim3(125, 16), 128>>>(
        bevsidx, bevmask,
        (const float*)d_in[17], (const float*)d_in[18], (const float*)d_in[19],
        (const float*)d_in[20], (const float*)d_in[21], (const float*)d_in[22]);

    bev2_kernel<<<500, 128, B2_SMEM_BYTES>>>(
        (const float*)d_in[23], (const float*)d_in[24], (const float*)d_in[25],
        (const float*)d_in[26], (const float*)d_in[27], (const float*)d_in[28],
        bevcoors, out);
}